// round 1
// baseline (speedup 1.0000x reference)
#include <cuda_runtime.h>
#include <cuda_bf16.h>
#include <math.h>

// Problem constants
#define B     16
#define CIN   256
#define COUT  256
#define NE    3
#define RC    16
#define H     64
#define W     64
#define KK    3

// Scratch (device globals -- no allocation allowed)
__device__ float g_pooled[B * CIN * 16];            // (b, c, 16) pooled 4x4 per channel
__device__ float g_route[B * NE * CIN];             // (b, k, c) routing weights
__device__ float g_wcomb[B * COUT * CIN * 9];       // (b, o, c, ky, kx) combined weights  ~37.7 MB

// ---------------------------------------------------------------------------
// Kernel A: adaptive avg pool to 4x4.  grid = B*CIN blocks, 256 threads.
// Each thread sums one 16-float contiguous segment; pooled = mean over 16x16.
// ---------------------------------------------------------------------------
__global__ void pool_kernel(const float* __restrict__ x) {
    __shared__ float seg[256];
    int bc  = blockIdx.x;            // b*CIN + c
    int t   = threadIdx.x;           // 0..255
    int row = t >> 2;                // 0..63
    int q   = t & 3;                 // 0..3 (column quarter)
    const float* base = x + ((size_t)bc * H + row) * W + q * 16;
    float s = 0.f;
    const float4* b4 = reinterpret_cast<const float4*>(base);
#pragma unroll
    for (int i = 0; i < 4; i++) {
        float4 v = b4[i];
        s += v.x + v.y + v.z + v.w;
    }
    seg[t] = s;
    __syncthreads();
    if (t < 16) {
        int pr = t >> 2, pc = t & 3;
        float acc = 0.f;
#pragma unroll
        for (int r = 0; r < 16; r++)
            acc += seg[(pr * 16 + r) * 4 + pc];
        g_pooled[bc * 16 + t] = acc * (1.0f / 256.0f);
    }
}

// ---------------------------------------------------------------------------
// Kernel B: routing MLP. grid = B blocks, 256 threads.
// y1[r, p] = relu( sum_c pooled[c,p] * rconv_w[r,c] + rconv_b[r] )   (16x16)
// y2[e]    = sigmoid( relu( sum_m y1flat[m] * fc_w[e,m] + fc_b[e] ) ) (768)
// ---------------------------------------------------------------------------
__global__ void route_kernel(const float* __restrict__ rconv_w,
                             const float* __restrict__ rconv_b,
                             const float* __restrict__ fc_w,
                             const float* __restrict__ fc_b) {
    __shared__ float sp[CIN * 16];   // pooled for this sample
    __shared__ float sy1[RC * 16];   // 256
    int b = blockIdx.x;
    int t = threadIdx.x;
    // load pooled (4096 floats)
#pragma unroll
    for (int i = 0; i < 16; i++)
        sp[t + i * 256] = g_pooled[b * CIN * 16 + t + i * 256];
    __syncthreads();
    // y1: 256 outputs, one per thread
    {
        int r = t >> 4;      // 0..15
        int p = t & 15;      // 0..15
        float s = rconv_b[r];
        const float* wrow = rconv_w + r * CIN;
#pragma unroll 8
        for (int c = 0; c < CIN; c++)
            s = fmaf(sp[c * 16 + p], wrow[c], s);
        sy1[r * 16 + p] = fmaxf(s, 0.f);
    }
    __syncthreads();
    // y2: 768 outputs, 3 per thread
#pragma unroll
    for (int kk = 0; kk < NE; kk++) {
        int e = kk * 256 + t;
        float s = fc_b[e];
        const float* wrow = fc_w + (size_t)e * 256;
#pragma unroll 8
        for (int m = 0; m < 256; m++)
            s = fmaf(sy1[m], wrow[m], s);
        s = fmaxf(s, 0.f);
        g_route[b * (NE * CIN) + e] = 1.0f / (1.0f + expf(-s));
    }
}

// ---------------------------------------------------------------------------
// Kernel C: combine expert weights.
// wcomb[b,o,c,t] = sum_k route[b,k,c] * ew[k,o,c,t]
// ---------------------------------------------------------------------------
__global__ void combine_kernel(const float* __restrict__ ew) {
    size_t idx = (size_t)blockIdx.x * blockDim.x + threadIdx.x;
    const size_t N = (size_t)B * COUT * CIN * 9;
    if (idx >= N) return;
    int t = idx % 9;
    int c = (idx / 9) % CIN;
    int o = (idx / (9 * CIN)) % COUT;
    int b = idx / ((size_t)9 * CIN * COUT);
    float s = 0.f;
#pragma unroll
    for (int k = 0; k < NE; k++) {
        float r = g_route[b * (NE * CIN) + k * CIN + c];
        float w = ew[(((size_t)k * COUT + o) * CIN + c) * 9 + t];
        s = fmaf(r, w, s);
    }
    g_wcomb[idx] = s;
}

// ---------------------------------------------------------------------------
// Kernel D: per-sample 3x3 conv, implicit GEMM.
// grid = (64 rows, COUT/64 tiles, B samples), 128 threads.
// Block computes out[b, ob..ob+64, y0, 0..64).
// Thread tile: 4 c_out x 8 px. BK = 8 input channels per chunk.
// ---------------------------------------------------------------------------
#define BK 8
__global__ __launch_bounds__(128, 4)
void conv_kernel(const float* __restrict__ x, float* __restrict__ out) {
    __shared__ __align__(16) float sx[BK][3][68];   // x halo tile: col cx -> xx = cx-1
    __shared__ float sw[64][73];                    // weight tile, padded rows

    int y0 = blockIdx.x;            // output row
    int ob = blockIdx.y * 64;       // c_out base
    int b  = blockIdx.z;            // sample
    int tid = threadIdx.x;
    int to = tid >> 3;              // 0..15 : c_out group
    int tp = tid & 7;               // 0..7  : pixel group (8 px each)

    float acc[4][8];
#pragma unroll
    for (int i = 0; i < 4; i++)
#pragma unroll
        for (int j = 0; j < 8; j++) acc[i][j] = 0.f;

    const float* xb = x + (size_t)b * CIN * H * W;
    const float* wb = g_wcomb + ((size_t)b * COUT + ob) * CIN * 9;

    for (int c0 = 0; c0 < CIN; c0 += BK) {
        // --- load x tile: BK ch x 3 rows x 68 cols (zero-padded halo) ---
        for (int i = tid; i < BK * 3 * 68; i += 128) {
            int cc = i / 204;
            int rem = i % 204;
            int d  = rem / 68;
            int cx = rem % 68;
            int iy = y0 + d - 1;
            int xx = cx - 1;
            float v = 0.f;
            if (iy >= 0 && iy < H && xx >= 0 && xx < W)
                v = xb[((size_t)(c0 + cc) * H + iy) * W + xx];
            sx[cc][d][cx] = v;
        }
        // --- load w tile: 64 c_out x (BK*9) ---
        for (int i = tid; i < 64 * 72; i += 128) {
            int oo = i / 72;
            int j  = i % 72;
            sw[oo][j] = wb[(size_t)oo * CIN * 9 + c0 * 9 + j];
        }
        __syncthreads();

        // --- compute ---
#pragma unroll
        for (int cc = 0; cc < BK; cc++) {
#pragma unroll
            for (int ky = 0; ky < 3; ky++) {
                const float* xrow = &sx[cc][ky][tp * 8];
                float xv[10];
                float4 v0 = *reinterpret_cast<const float4*>(xrow);
                float4 v1 = *reinterpret_cast<const float4*>(xrow + 4);
                xv[0] = v0.x; xv[1] = v0.y; xv[2] = v0.z; xv[3] = v0.w;
                xv[4] = v1.x; xv[5] = v1.y; xv[6] = v1.z; xv[7] = v1.w;
                xv[8] = xrow[8]; xv[9] = xrow[9];
                float wv[4][3];
#pragma unroll
                for (int i = 0; i < 4; i++)
#pragma unroll
                    for (int kx = 0; kx < 3; kx++)
                        wv[i][kx] = sw[to * 4 + i][cc * 9 + ky * 3 + kx];
#pragma unroll
                for (int kx = 0; kx < 3; kx++)
#pragma unroll
                    for (int i = 0; i < 4; i++)
#pragma unroll
                        for (int j = 0; j < 8; j++)
                            acc[i][j] = fmaf(wv[i][kx], xv[j + kx], acc[i][j]);
            }
        }
        __syncthreads();
    }

    // --- write out ---
#pragma unroll
    for (int i = 0; i < 4; i++) {
        int o = ob + to * 4 + i;
        float* op = out + (((size_t)b * COUT + o) * H + y0) * W + tp * 8;
        float4 r0 = make_float4(acc[i][0], acc[i][1], acc[i][2], acc[i][3]);
        float4 r1 = make_float4(acc[i][4], acc[i][5], acc[i][6], acc[i][7]);
        reinterpret_cast<float4*>(op)[0] = r0;
        reinterpret_cast<float4*>(op)[1] = r1;
    }
}

// ---------------------------------------------------------------------------
extern "C" void kernel_launch(void* const* d_in, const int* in_sizes, int n_in,
                              void* d_out, int out_size) {
    const float* x    = (const float*)d_in[0];
    const float* ew   = (const float*)d_in[1];
    const float* rcw  = (const float*)d_in[2];
    const float* rcb  = (const float*)d_in[3];
    const float* fcw  = (const float*)d_in[4];
    const float* fcb  = (const float*)d_in[5];
    float* out = (float*)d_out;

    // A: pooling
    pool_kernel<<<B * CIN, 256>>>(x);
    // B: routing MLP
    route_kernel<<<B, 256>>>(rcw, rcb, fcw, fcb);
    // C: combine expert weights
    {
        const size_t N = (size_t)B * COUT * CIN * 9;
        int threads = 256;
        int blocks = (int)((N + threads - 1) / threads);
        combine_kernel<<<blocks, threads>>>(ew);
    }
    // D: conv
    {
        dim3 grid(H, COUT / 64, B);
        conv_kernel<<<grid, 128>>>(x, out);
    }
}

// round 3
// speedup vs baseline: 4.0094x; 4.0094x over previous
#include <cuda_runtime.h>
#include <cuda_fp16.h>
#include <cstdint>
#include <math.h>

// Problem constants
#define B     16
#define CIN   256
#define COUT  256
#define NE    3
#define RC    16
#define H     64
#define W     64

// ---------------------------------------------------------------------------
// Device scratch
// ---------------------------------------------------------------------------
__device__ float g_pooled[B * CIN * 16];
__device__ float g_route[B * NE * CIN];

// combined weights fp16: [b][half][pos9][chunk4][o128][c64]
#define NWH (16*2*9*4*128*64)
__device__ __align__(16) __half g_wh[NWH];

// padded transposed x, fp16 hi/lo: [b][yy66][xx66][c256]
#define NXT (16*66*66*256)
__device__ __align__(16) __half g_xt_h[NXT];
__device__ __align__(16) __half g_xt_l[NXT];

// ---------------------------------------------------------------------------
__device__ __forceinline__ uint32_t smem_u32(const void* p) {
    uint32_t a;
    asm("{ .reg .u64 t; cvta.to.shared.u64 t, %1; cvt.u32.u64 %0, t; }" : "=r"(a) : "l"(p));
    return a;
}
__device__ __forceinline__ void cp_async16(uint32_t dst, const void* src) {
    asm volatile("cp.async.cg.shared.global [%0], [%1], 16;" :: "r"(dst), "l"(src));
}
__device__ __forceinline__ void cp_commit() { asm volatile("cp.async.commit_group;"); }
__device__ __forceinline__ void cp_wait_all() { asm volatile("cp.async.wait_group 0;"); }

__device__ __forceinline__ void ldsm_x4(uint32_t& r0, uint32_t& r1, uint32_t& r2, uint32_t& r3,
                                        uint32_t addr) {
    asm volatile("ldmatrix.sync.aligned.m8n8.x4.shared.b16 {%0,%1,%2,%3}, [%4];"
                 : "=r"(r0), "=r"(r1), "=r"(r2), "=r"(r3) : "r"(addr));
}
__device__ __forceinline__ void mma16816(float& c0, float& c1, float& c2, float& c3,
                                         uint32_t a0, uint32_t a1, uint32_t a2, uint32_t a3,
                                         uint32_t b0, uint32_t b1) {
    asm volatile("mma.sync.aligned.m16n8k16.row.col.f32.f16.f16.f32 "
                 "{%0,%1,%2,%3}, {%4,%5,%6,%7}, {%8,%9}, {%0,%1,%2,%3};"
                 : "+f"(c0), "+f"(c1), "+f"(c2), "+f"(c3)
                 : "r"(a0), "r"(a1), "r"(a2), "r"(a3), "r"(b0), "r"(b1));
}

// ---------------------------------------------------------------------------
// Kernel A: adaptive avg pool to 4x4
// ---------------------------------------------------------------------------
__global__ void pool_kernel(const float* __restrict__ x) {
    __shared__ float seg[256];
    int bc = blockIdx.x, t = threadIdx.x;
    int row = t >> 2, q = t & 3;
    const float4* b4 = reinterpret_cast<const float4*>(x + ((size_t)bc * H + row) * W + q * 16);
    float s = 0.f;
#pragma unroll
    for (int i = 0; i < 4; i++) { float4 v = b4[i]; s += v.x + v.y + v.z + v.w; }
    seg[t] = s;
    __syncthreads();
    if (t < 16) {
        int pr = t >> 2, pc = t & 3;
        float acc = 0.f;
#pragma unroll
        for (int r = 0; r < 16; r++) acc += seg[(pr * 16 + r) * 4 + pc];
        g_pooled[bc * 16 + t] = acc * (1.0f / 256.0f);
    }
}

// ---------------------------------------------------------------------------
// Kernel B: routing MLP
// ---------------------------------------------------------------------------
__global__ void route_kernel(const float* __restrict__ rconv_w,
                             const float* __restrict__ rconv_b,
                             const float* __restrict__ fc_w,
                             const float* __restrict__ fc_b) {
    __shared__ float sp[CIN * 16];
    __shared__ float sy1[RC * 16];
    int b = blockIdx.x, t = threadIdx.x;
#pragma unroll
    for (int i = 0; i < 16; i++)
        sp[t + i * 256] = g_pooled[b * CIN * 16 + t + i * 256];
    __syncthreads();
    {
        int r = t >> 4, p = t & 15;
        float s = rconv_b[r];
        const float* wrow = rconv_w + r * CIN;
#pragma unroll 8
        for (int c = 0; c < CIN; c++) s = fmaf(sp[c * 16 + p], wrow[c], s);
        sy1[r * 16 + p] = fmaxf(s, 0.f);
    }
    __syncthreads();
#pragma unroll
    for (int kk = 0; kk < NE; kk++) {
        int e = kk * 256 + t;
        float s = fc_b[e];
        const float* wrow = fc_w + (size_t)e * 256;
#pragma unroll 8
        for (int m = 0; m < 256; m++) s = fmaf(sy1[m], wrow[m], s);
        s = fmaxf(s, 0.f);
        g_route[b * (NE * CIN) + e] = 1.0f / (1.0f + expf(-s));
    }
}

// ---------------------------------------------------------------------------
// Kernel C: combine expert weights -> fp16 in A layout
// ---------------------------------------------------------------------------
__global__ void wsplit_kernel(const float* __restrict__ ew) {
    int idx = blockIdx.x * blockDim.x + threadIdx.x;   // 0..65535
    int o = idx >> 8, c = idx & 255;
    float w0[3][9];
#pragma unroll
    for (int k = 0; k < 3; k++)
#pragma unroll
        for (int t = 0; t < 9; t++)
            w0[k][t] = ew[(((size_t)k * COUT + o) * CIN + c) * 9 + t];
    int half = o >> 7, m = o & 127, q = c >> 6, cc = c & 63;
    for (int b = 0; b < B; b++) {
        float r0 = g_route[b * 768 + 0 * 256 + c];
        float r1 = g_route[b * 768 + 1 * 256 + c];
        float r2 = g_route[b * 768 + 2 * 256 + c];
#pragma unroll
        for (int t = 0; t < 9; t++) {
            float w = fmaf(r2, w0[2][t], fmaf(r1, w0[1][t], r0 * w0[0][t]));
            size_t off = ((((size_t)(b * 2 + half) * 9 + t) * 4 + q) * 128 + m) * 64 + cc;
            g_wh[off] = __float2half(w);
        }
    }
}

// ---------------------------------------------------------------------------
// Kernel Z: zero the padded x arrays
// ---------------------------------------------------------------------------
__global__ void zero_xt() {
    size_t i = (size_t)blockIdx.x * 256 + threadIdx.x;
    if (i < NXT / 8) {
        uint4 z = make_uint4(0, 0, 0, 0);
        reinterpret_cast<uint4*>(g_xt_h)[i] = z;
        reinterpret_cast<uint4*>(g_xt_l)[i] = z;
    }
}

// ---------------------------------------------------------------------------
// Kernel X: transpose + pad + fp16 hi/lo split of x  ->  [b][yy][xx][c]
// ---------------------------------------------------------------------------
__global__ void xprep_kernel(const float* __restrict__ x) {
    __shared__ float ti[32][65];
    int c0 = blockIdx.x * 32, y = blockIdx.y, b = blockIdx.z;
    int t = threadIdx.x;
    {
        int cc = t >> 3, xg = t & 7;
        const float4* src = reinterpret_cast<const float4*>(
            x + (((size_t)b * CIN + c0 + cc) * H + y) * W + xg * 8);
        float4 v0 = src[0], v1 = src[1];
        ti[cc][xg * 8 + 0] = v0.x; ti[cc][xg * 8 + 1] = v0.y;
        ti[cc][xg * 8 + 2] = v0.z; ti[cc][xg * 8 + 3] = v0.w;
        ti[cc][xg * 8 + 4] = v1.x; ti[cc][xg * 8 + 5] = v1.y;
        ti[cc][xg * 8 + 6] = v1.z; ti[cc][xg * 8 + 7] = v1.w;
    }
    __syncthreads();
    int xx = t >> 2, cg = t & 3;
    __half h8[8], l8[8];
#pragma unroll
    for (int j = 0; j < 8; j++) {
        float v = ti[cg * 8 + j][xx];
        __half h = __float2half(v);
        h8[j] = h;
        l8[j] = __float2half(v - __half2float(h));
    }
    size_t off = (((size_t)b * 66 + (y + 1)) * 66 + (xx + 1)) * 256 + c0 + cg * 8;
    *reinterpret_cast<uint4*>(&g_xt_h[off]) = *reinterpret_cast<const uint4*>(h8);
    *reinterpret_cast<uint4*>(&g_xt_l[off]) = *reinterpret_cast<const uint4*>(l8);
}

// ---------------------------------------------------------------------------
// Main conv kernel: warp-MMA fp16 shift-GEMM.
// CTA: M=128 couts x N=128 px (2 output rows). 8 warps (2x4), warp 64x32.
// K loop: 4 chunks of 64 ch; per chunk one halo x-tile serves all 9 (ky,kx).
// ---------------------------------------------------------------------------
#define PADK 72
#define SB_HALVES (4 * 66 * PADK)          // 19008 halves
#define SB_BYTES  (SB_HALVES * 2)          // 38016 B
#define SA_HALVES (128 * PADK)             // 9216 halves per buffer
#define SA_BYTES  (SA_HALVES * 2)          // 18432 B
#define SMEM_TOTAL (2 * SB_BYTES + 2 * SA_BYTES)   // 112896 B

__global__ void __launch_bounds__(256, 1)
conv_mma_kernel(float* __restrict__ out) {
    extern __shared__ __align__(128) char smem[];
    uint32_t sBh = smem_u32(smem);
    uint32_t sBl = sBh + SB_BYTES;
    uint32_t sA  = sBl + SB_BYTES;          // two buffers of SA_BYTES

    int tid = threadIdx.x;
    int wid = tid >> 5, l = tid & 31;
    int warp_m = wid >> 2;                   // 0..1
    int warp_n = wid & 3;                    // 0..3

    int ntile = blockIdx.x;                  // 0..31
    int half  = blockIdx.y;                  // 0..1
    int b     = blockIdx.z;                  // 0..15
    int y0    = ntile * 2;                   // output rows y0, y0+1

    // lane-invariant ldmatrix offsets (in halves)
    int aRow = warp_m * 64 + ((l >> 3) & 1) * 8 + (l & 7);
    int aK   = ((l >> 4) & 1) * 8;
    int aLaneOff = aRow * PADK + aK;                      // + mf*16*PADK + ks*16

    int bLaneOff[2];
#pragma unroll
    for (int g = 0; g < 2; g++) {
        int pix = warp_n * 32 + g * 16 + ((l >> 4) & 1) * 8 + (l & 7);
        int rb = pix >> 6, cb = pix & 63;
        bLaneOff[g] = (rb * 66 + cb) * PADK + ((l >> 3) & 1) * 8;   // + (ky*66+kx)*PADK + ks*16
    }

    float acc[4][4][4];
#pragma unroll
    for (int i = 0; i < 4; i++)
#pragma unroll
        for (int j = 0; j < 4; j++)
#pragma unroll
            for (int k = 0; k < 4; k++) acc[i][j][k] = 0.f;

    const __half* xth = g_xt_h;
    const __half* xtl = g_xt_l;
    const __half* wbase = g_wh + (((size_t)(b * 2 + half) * 9) * 4) * 128 * 64;

    for (int cc = 0; cc < 4; cc++) {
        int c0 = cc * 64;
        // ---- load B halo tile (4 rows x 66 px x 64c), hi + lo ----
        for (int i = tid; i < 264 * 8; i += 256) {
            int row = i >> 3, seg = i & 7;
            int gy = y0 + (row / 66), gx = row % 66;
            size_t goff = (((size_t)b * 66 + gy) * 66 + gx) * 256 + c0 + seg * 8;
            uint32_t soff = (uint32_t)(row * PADK + seg * 8) * 2;
            cp_async16(sBh + soff, xth + goff);
            cp_async16(sBl + soff, xtl + goff);
        }
        // ---- load A for pos 0 into buffer 0 ----
        for (int i = tid; i < 1024; i += 256) {
            int row = i >> 3, seg = i & 7;
            const __half* src = wbase + (((size_t)(0 * 4 + cc)) * 128 + row) * 64 + seg * 8;
            cp_async16(sA + (uint32_t)(row * PADK + seg * 8) * 2, src);
        }
        cp_commit();
        cp_wait_all();
        __syncthreads();

        for (int pos = 0; pos < 9; pos++) {
            // prefetch A for pos+1
            if (pos + 1 < 9) {
                uint32_t abuf = sA + ((pos + 1) & 1) * SA_BYTES;
                for (int i = tid; i < 1024; i += 256) {
                    int row = i >> 3, seg = i & 7;
                    const __half* src = wbase + (((size_t)((pos + 1) * 4 + cc)) * 128 + row) * 64 + seg * 8;
                    cp_async16(abuf + (uint32_t)(row * PADK + seg * 8) * 2, src);
                }
                cp_commit();
            }

            int ky = pos / 3, kx = pos % 3;
            int posOff = (ky * 66 + kx) * PADK;
            uint32_t aBase = sA + (pos & 1) * SA_BYTES;

#pragma unroll
            for (int ks = 0; ks < 4; ks++) {
                uint32_t a0[4], a1[4], a2[4], a3[4];
#pragma unroll
                for (int mf = 0; mf < 4; mf++) {
                    uint32_t addr = aBase + (uint32_t)(aLaneOff + mf * 16 * PADK + ks * 16) * 2;
                    ldsm_x4(a0[mf], a1[mf], a2[mf], a3[mf], addr);
                }
                uint32_t bh[8], bl[8];
#pragma unroll
                for (int g = 0; g < 2; g++) {
                    uint32_t off = (uint32_t)(bLaneOff[g] + posOff + ks * 16) * 2;
                    ldsm_x4(bh[g * 4 + 0], bh[g * 4 + 1], bh[g * 4 + 2], bh[g * 4 + 3], sBh + off);
                    ldsm_x4(bl[g * 4 + 0], bl[g * 4 + 1], bl[g * 4 + 2], bl[g * 4 + 3], sBl + off);
                }
#pragma unroll
                for (int mf = 0; mf < 4; mf++) {
#pragma unroll
                    for (int nf = 0; nf < 4; nf++) {
                        // nf -> (g = nf>>1, pair = nf&1): regs {2*pair, 2*pair+1} of group g
                        int g = nf >> 1, pr = (nf & 1) * 2;
                        mma16816(acc[mf][nf][0], acc[mf][nf][1], acc[mf][nf][2], acc[mf][nf][3],
                                 a0[mf], a1[mf], a2[mf], a3[mf],
                                 bh[g * 4 + pr], bh[g * 4 + pr + 1]);
                        mma16816(acc[mf][nf][0], acc[mf][nf][1], acc[mf][nf][2], acc[mf][nf][3],
                                 a0[mf], a1[mf], a2[mf], a3[mf],
                                 bl[g * 4 + pr], bl[g * 4 + pr + 1]);
                    }
                }
            }
            cp_wait_all();
            __syncthreads();
        }
    }

    // ---- epilogue ----
#pragma unroll
    for (int mf = 0; mf < 4; mf++) {
        int o = half * 128 + warp_m * 64 + mf * 16 + (l >> 2);
#pragma unroll
        for (int nf = 0; nf < 4; nf++) {
            int p = warp_n * 32 + nf * 8 + (l & 3) * 2;
            int y = y0 + (p >> 6), xcol = p & 63;
            float* base0 = out + (((size_t)b * COUT + o) * H + y) * W + xcol;
            float* base1 = out + (((size_t)b * COUT + o + 8) * H + y) * W + xcol;
            reinterpret_cast<float2*>(base0)[0] = make_float2(acc[mf][nf][0], acc[mf][nf][1]);
            reinterpret_cast<float2*>(base1)[0] = make_float2(acc[mf][nf][2], acc[mf][nf][3]);
        }
    }
}

// ---------------------------------------------------------------------------
extern "C" void kernel_launch(void* const* d_in, const int* in_sizes, int n_in,
                              void* d_out, int out_size) {
    const float* x   = (const float*)d_in[0];
    const float* ew  = (const float*)d_in[1];
    const float* rcw = (const float*)d_in[2];
    const float* rcb = (const float*)d_in[3];
    const float* fcw = (const float*)d_in[4];
    const float* fcb = (const float*)d_in[5];
    float* out = (float*)d_out;

    static bool attr_set = false;
    if (!attr_set) {
        cudaFuncSetAttribute(conv_mma_kernel, cudaFuncAttributeMaxDynamicSharedMemorySize,
                             SMEM_TOTAL);
        attr_set = true;
    }

    zero_xt<<<(NXT / 8 + 255) / 256, 256>>>();
    pool_kernel<<<B * CIN, 256>>>(x);
    route_kernel<<<B, 256>>>(rcw, rcb, fcw, fcb);
    wsplit_kernel<<<256, 256>>>(ew);
    {
        dim3 g(8, 64, 16);
        xprep_kernel<<<g, 256>>>(x);
    }
    {
        dim3 g(32, 2, 16);
        conv_mma_kernel<<<g, 256, SMEM_TOTAL>>>(out);
    }
}

// round 4
// speedup vs baseline: 5.5591x; 1.3865x over previous
#include <cuda_runtime.h>
#include <cuda_fp16.h>
#include <cstdint>
#include <math.h>

// Problem constants
#define B     16
#define CIN   256
#define COUT  256
#define NE    3
#define RC    16
#define H     64
#define W     64

// ---------------------------------------------------------------------------
// Device scratch
// ---------------------------------------------------------------------------
__device__ float g_pooled[B * CIN * 16];
__device__ float g_route[B * NE * CIN];

// combined weights fp16: [b][half][pos9][chunk4][o128][c64]
#define NWH (16*2*9*4*128*64)
__device__ __align__(16) __half g_wh[NWH];

// padded transposed x, fp16: [b][yy66][xx66][c256]
#define NXT (16*66*66*256)
__device__ __align__(16) __half g_xt_h[NXT];

// ---------------------------------------------------------------------------
__device__ __forceinline__ uint32_t smem_u32(const void* p) {
    uint32_t a;
    asm("{ .reg .u64 t; cvta.to.shared.u64 t, %1; cvt.u32.u64 %0, t; }" : "=r"(a) : "l"(p));
    return a;
}
__device__ __forceinline__ void cp_async16(uint32_t dst, const void* src) {
    asm volatile("cp.async.cg.shared.global [%0], [%1], 16;" :: "r"(dst), "l"(src));
}
__device__ __forceinline__ void cp_commit() { asm volatile("cp.async.commit_group;"); }
__device__ __forceinline__ void cp_wait0() { asm volatile("cp.async.wait_group 0;"); }
__device__ __forceinline__ void cp_wait1() { asm volatile("cp.async.wait_group 1;"); }

__device__ __forceinline__ void ldsm_x4(uint32_t& r0, uint32_t& r1, uint32_t& r2, uint32_t& r3,
                                        uint32_t addr) {
    asm volatile("ldmatrix.sync.aligned.m8n8.x4.shared.b16 {%0,%1,%2,%3}, [%4];"
                 : "=r"(r0), "=r"(r1), "=r"(r2), "=r"(r3) : "r"(addr));
}
__device__ __forceinline__ void mma16816(float& c0, float& c1, float& c2, float& c3,
                                         uint32_t a0, uint32_t a1, uint32_t a2, uint32_t a3,
                                         uint32_t b0, uint32_t b1) {
    asm volatile("mma.sync.aligned.m16n8k16.row.col.f32.f16.f16.f32 "
                 "{%0,%1,%2,%3}, {%4,%5,%6,%7}, {%8,%9}, {%0,%1,%2,%3};"
                 : "+f"(c0), "+f"(c1), "+f"(c2), "+f"(c3)
                 : "r"(a0), "r"(a1), "r"(a2), "r"(a3), "r"(b0), "r"(b1));
}

// ---------------------------------------------------------------------------
// Kernel A: adaptive avg pool to 4x4
// ---------------------------------------------------------------------------
__global__ void pool_kernel(const float* __restrict__ x) {
    __shared__ float seg[256];
    int bc = blockIdx.x, t = threadIdx.x;
    int row = t >> 2, q = t & 3;
    const float4* b4 = reinterpret_cast<const float4*>(x + ((size_t)bc * H + row) * W + q * 16);
    float s = 0.f;
#pragma unroll
    for (int i = 0; i < 4; i++) { float4 v = b4[i]; s += v.x + v.y + v.z + v.w; }
    seg[t] = s;
    __syncthreads();
    if (t < 16) {
        int pr = t >> 2, pc = t & 3;
        float acc = 0.f;
#pragma unroll
        for (int r = 0; r < 16; r++) acc += seg[(pr * 16 + r) * 4 + pc];
        g_pooled[bc * 16 + t] = acc * (1.0f / 256.0f);
    }
}

// ---------------------------------------------------------------------------
// Kernel B: routing MLP
// ---------------------------------------------------------------------------
__global__ void route_kernel(const float* __restrict__ rconv_w,
                             const float* __restrict__ rconv_b,
                             const float* __restrict__ fc_w,
                             const float* __restrict__ fc_b) {
    __shared__ float sp[CIN * 16];
    __shared__ float sy1[RC * 16];
    int b = blockIdx.x, t = threadIdx.x;
#pragma unroll
    for (int i = 0; i < 16; i++)
        sp[t + i * 256] = g_pooled[b * CIN * 16 + t + i * 256];
    __syncthreads();
    {
        int r = t >> 4, p = t & 15;
        float s = rconv_b[r];
        const float* wrow = rconv_w + r * CIN;
#pragma unroll 8
        for (int c = 0; c < CIN; c++) s = fmaf(sp[c * 16 + p], wrow[c], s);
        sy1[r * 16 + p] = fmaxf(s, 0.f);
    }
    __syncthreads();
#pragma unroll
    for (int kk = 0; kk < NE; kk++) {
        int e = kk * 256 + t;
        float s = fc_b[e];
        const float* wrow = fc_w + (size_t)e * 256;
#pragma unroll 8
        for (int m = 0; m < 256; m++) s = fmaf(sy1[m], wrow[m], s);
        s = fmaxf(s, 0.f);
        g_route[b * (NE * CIN) + e] = 1.0f / (1.0f + expf(-s));
    }
}

// ---------------------------------------------------------------------------
// Kernel C: combine expert weights -> fp16 in A layout
// ---------------------------------------------------------------------------
__global__ void wsplit_kernel(const float* __restrict__ ew) {
    int idx = blockIdx.x * blockDim.x + threadIdx.x;   // 0..65535
    int o = idx >> 8, c = idx & 255;
    float w0[3][9];
#pragma unroll
    for (int k = 0; k < 3; k++)
#pragma unroll
        for (int t = 0; t < 9; t++)
            w0[k][t] = ew[(((size_t)k * COUT + o) * CIN + c) * 9 + t];
    int half = o >> 7, m = o & 127, q = c >> 6, cc = c & 63;
    for (int b = 0; b < B; b++) {
        float r0 = g_route[b * 768 + 0 * 256 + c];
        float r1 = g_route[b * 768 + 1 * 256 + c];
        float r2 = g_route[b * 768 + 2 * 256 + c];
#pragma unroll
        for (int t = 0; t < 9; t++) {
            float w = fmaf(r2, w0[2][t], fmaf(r1, w0[1][t], r0 * w0[0][t]));
            size_t off = ((((size_t)(b * 2 + half) * 9 + t) * 4 + q) * 128 + m) * 64 + cc;
            g_wh[off] = __float2half(w);
        }
    }
}

// ---------------------------------------------------------------------------
// Kernel Z: zero only the padded borders of g_xt_h (interior written by xprep)
// Covers yy in {0,65} full rows, and xx in {0,65} full columns (corners twice).
// thread -> (b, side4, idx66, seg32); seg = 8 halves (uint4)
// ---------------------------------------------------------------------------
__global__ void zero_border() {
    int i = blockIdx.x * 256 + threadIdx.x;
    int total = 16 * 4 * 66 * 32;
    if (i >= total) return;
    int seg = i & 31;
    int idx = (i >> 5) % 66;
    int side = (i >> 5) / 66 % 4;
    int b = i / (4 * 66 * 32);
    int yy, xx;
    if (side == 0)      { yy = 0;   xx = idx; }
    else if (side == 1) { yy = 65;  xx = idx; }
    else if (side == 2) { yy = idx; xx = 0;  }
    else                { yy = idx; xx = 65; }
    size_t off = (((size_t)b * 66 + yy) * 66 + xx) * 256 + seg * 8;
    reinterpret_cast<uint4*>(&g_xt_h[off])[0] = make_uint4(0, 0, 0, 0);
}

// ---------------------------------------------------------------------------
// Kernel X: transpose + pad + fp16 convert of x  ->  [b][yy][xx][c]
// ---------------------------------------------------------------------------
__global__ void xprep_kernel(const float* __restrict__ x) {
    __shared__ float ti[32][65];
    int c0 = blockIdx.x * 32, y = blockIdx.y, b = blockIdx.z;
    int t = threadIdx.x;
    {
        int cc = t >> 3, xg = t & 7;
        const float4* src = reinterpret_cast<const float4*>(
            x + (((size_t)b * CIN + c0 + cc) * H + y) * W + xg * 8);
        float4 v0 = src[0], v1 = src[1];
        ti[cc][xg * 8 + 0] = v0.x; ti[cc][xg * 8 + 1] = v0.y;
        ti[cc][xg * 8 + 2] = v0.z; ti[cc][xg * 8 + 3] = v0.w;
        ti[cc][xg * 8 + 4] = v1.x; ti[cc][xg * 8 + 5] = v1.y;
        ti[cc][xg * 8 + 6] = v1.z; ti[cc][xg * 8 + 7] = v1.w;
    }
    __syncthreads();
    int xx = t >> 2, cg = t & 3;
    __half h8[8];
#pragma unroll
    for (int j = 0; j < 8; j++)
        h8[j] = __float2half(ti[cg * 8 + j][xx]);
    size_t off = (((size_t)b * 66 + (y + 1)) * 66 + (xx + 1)) * 256 + c0 + cg * 8;
    *reinterpret_cast<uint4*>(&g_xt_h[off]) = *reinterpret_cast<const uint4*>(h8);
}

// ---------------------------------------------------------------------------
// Main conv kernel: warp-MMA fp16 shift-GEMM, single-term.
// CTA: M=128 couts x N=128 px (2 output rows). 8 warps (2x4), warp 64x32.
// B halo tile double-buffered across cc; A double-buffered across pos.
// ---------------------------------------------------------------------------
#define PADK 72
#define SB_HALVES (4 * 66 * PADK)          // 19008 halves
#define SB_BYTES  (SB_HALVES * 2)          // 38016 B
#define SA_HALVES (128 * PADK)             // 9216 halves
#define SA_BYTES  (SA_HALVES * 2)          // 18432 B
#define SMEM_TOTAL (2 * SB_BYTES + 2 * SA_BYTES)   // 112896 B

__global__ void __launch_bounds__(256, 1)
conv_mma_kernel(float* __restrict__ out) {
    extern __shared__ __align__(128) char smem[];
    uint32_t sB = smem_u32(smem);            // two buffers of SB_BYTES
    uint32_t sA = sB + 2 * SB_BYTES;         // two buffers of SA_BYTES

    int tid = threadIdx.x;
    int wid = tid >> 5, l = tid & 31;
    int warp_m = wid >> 2;                   // 0..1
    int warp_n = wid & 3;                    // 0..3

    int ntile = blockIdx.x;                  // 0..31
    int half  = blockIdx.y;                  // 0..1
    int b     = blockIdx.z;                  // 0..15
    int y0    = ntile * 2;

    int aRow = warp_m * 64 + ((l >> 3) & 1) * 8 + (l & 7);
    int aK   = ((l >> 4) & 1) * 8;
    int aLaneOff = aRow * PADK + aK;

    int bLaneOff[2];
#pragma unroll
    for (int g = 0; g < 2; g++) {
        int pix = warp_n * 32 + g * 16 + ((l >> 4) & 1) * 8 + (l & 7);
        int rb = pix >> 6, cb = pix & 63;
        bLaneOff[g] = (rb * 66 + cb) * PADK + ((l >> 3) & 1) * 8;
    }

    float acc[4][4][4];
#pragma unroll
    for (int i = 0; i < 4; i++)
#pragma unroll
        for (int j = 0; j < 4; j++)
#pragma unroll
            for (int k = 0; k < 4; k++) acc[i][j][k] = 0.f;

    const __half* wbase = g_wh + (size_t)(b * 2 + half) * 9 * 4 * 128 * 64;

    // helpers as lambdas
    auto loadB = [&](int cc, int buf) {
        uint32_t dst = sB + buf * SB_BYTES;
        int c0 = cc * 64;
        for (int i = tid; i < 264 * 8; i += 256) {
            int row = i >> 3, seg = i & 7;
            int gy = y0 + (row / 66), gx = row % 66;
            size_t goff = (((size_t)b * 66 + gy) * 66 + gx) * 256 + c0 + seg * 8;
            cp_async16(dst + (uint32_t)(row * PADK + seg * 8) * 2, g_xt_h + goff);
        }
    };
    auto loadA = [&](int pos, int cc, int buf) {
        uint32_t dst = sA + buf * SA_BYTES;
        for (int i = tid; i < 1024; i += 256) {
            int row = i >> 3, seg = i & 7;
            const __half* src = wbase + (((size_t)(pos * 4 + cc)) * 128 + row) * 64 + seg * 8;
            cp_async16(dst + (uint32_t)(row * PADK + seg * 8) * 2, src);
        }
    };

    // prologue: B(0) -> buf0, A(0,0) -> buf0
    loadB(0, 0);
    loadA(0, 0, 0);
    cp_commit();
    cp_wait0();
    __syncthreads();

    for (int cc = 0; cc < 4; cc++) {
        for (int pos = 0; pos < 9; pos++) {
            int step = cc * 9 + pos;
            uint32_t aBase = sA + (step & 1) * SA_BYTES;
            uint32_t bBase = sB + (cc & 1) * SB_BYTES;
            bool bpend = false;

            // prefetches
            if (pos < 8) {
                loadA(pos + 1, cc, (step + 1) & 1);
                cp_commit();
                if (pos == 7 && cc < 3) {
                    loadB(cc + 1, (cc + 1) & 1);
                    cp_commit();
                    bpend = true;          // leave B pending this step
                }
            } else if (cc < 3) {
                loadA(0, cc + 1, (step + 1) & 1);
                cp_commit();
            }

            int ky = pos / 3, kx = pos % 3;
            int posOff = (ky * 66 + kx) * PADK;

#pragma unroll
            for (int ks = 0; ks < 4; ks++) {
                uint32_t a0[4], a1[4], a2[4], a3[4];
#pragma unroll
                for (int mf = 0; mf < 4; mf++) {
                    uint32_t addr = aBase + (uint32_t)(aLaneOff + mf * 16 * PADK + ks * 16) * 2;
                    ldsm_x4(a0[mf], a1[mf], a2[mf], a3[mf], addr);
                }
                uint32_t bh[8];
#pragma unroll
                for (int g = 0; g < 2; g++) {
                    uint32_t off = (uint32_t)(bLaneOff[g] + posOff + ks * 16) * 2;
                    ldsm_x4(bh[g * 4 + 0], bh[g * 4 + 1], bh[g * 4 + 2], bh[g * 4 + 3], bBase + off);
                }
#pragma unroll
                for (int mf = 0; mf < 4; mf++) {
#pragma unroll
                    for (int nf = 0; nf < 4; nf++) {
                        int g = nf >> 1, pr = (nf & 1) * 2;
                        mma16816(acc[mf][nf][0], acc[mf][nf][1], acc[mf][nf][2], acc[mf][nf][3],
                                 a0[mf], a1[mf], a2[mf], a3[mf],
                                 bh[g * 4 + pr], bh[g * 4 + pr + 1]);
                    }
                }
            }

            if (bpend) cp_wait1();   // A(pos8) done; B(cc+1) may stay in flight
            else       cp_wait0();
            __syncthreads();
        }
    }

    // ---- epilogue ----
#pragma unroll
    for (int mf = 0; mf < 4; mf++) {
        int o = half * 128 + warp_m * 64 + mf * 16 + (l >> 2);
#pragma unroll
        for (int nf = 0; nf < 4; nf++) {
            int p = warp_n * 32 + nf * 8 + (l & 3) * 2;
            int y = y0 + (p >> 6), xcol = p & 63;
            float* base0 = out + (((size_t)b * COUT + o) * H + y) * W + xcol;
            float* base1 = out + (((size_t)b * COUT + o + 8) * H + y) * W + xcol;
            reinterpret_cast<float2*>(base0)[0] = make_float2(acc[mf][nf][0], acc[mf][nf][1]);
            reinterpret_cast<float2*>(base1)[0] = make_float2(acc[mf][nf][2], acc[mf][nf][3]);
        }
    }
}

// ---------------------------------------------------------------------------
extern "C" void kernel_launch(void* const* d_in, const int* in_sizes, int n_in,
                              void* d_out, int out_size) {
    const float* x   = (const float*)d_in[0];
    const float* ew  = (const float*)d_in[1];
    const float* rcw = (const float*)d_in[2];
    const float* rcb = (const float*)d_in[3];
    const float* fcw = (const float*)d_in[4];
    const float* fcb = (const float*)d_in[5];
    float* out = (float*)d_out;

    static bool attr_set = false;
    if (!attr_set) {
        cudaFuncSetAttribute(conv_mma_kernel, cudaFuncAttributeMaxDynamicSharedMemorySize,
                             SMEM_TOTAL);
        attr_set = true;
    }

    {
        int total = 16 * 4 * 66 * 32;
        zero_border<<<(total + 255) / 256, 256>>>();
    }
    pool_kernel<<<B * CIN, 256>>>(x);
    route_kernel<<<B, 256>>>(rcw, rcb, fcw, fcb);
    wsplit_kernel<<<256, 256>>>(ew);
    {
        dim3 g(8, 64, 16);
        xprep_kernel<<<g, 256>>>(x);
    }
    {
        dim3 g(32, 2, 16);
        conv_mma_kernel<<<g, 256, SMEM_TOTAL>>>(out);
    }
}

// round 5
// speedup vs baseline: 6.3649x; 1.1450x over previous
#include <cuda_runtime.h>
#include <cuda_fp16.h>
#include <cstdint>
#include <math.h>

// Problem constants
#define B     16
#define CIN   256
#define COUT  256
#define NE    3
#define RC    16
#define H     64
#define W     64

// ---------------------------------------------------------------------------
// Device scratch
// ---------------------------------------------------------------------------
__device__ float g_pooled[B * CIN * 16];
__device__ float g_route[B * NE * CIN];

// combined weights fp16: [b][half][pos9][chunk4][o128][c64]
#define NWH (16*2*9*4*128*64)
__device__ __align__(16) __half g_wh[NWH];

// padded transposed x, fp16: [b][yy66][xx66][c256]
#define NXT (16*66*66*256)
__device__ __align__(16) __half g_xt_h[NXT];

// ---------------------------------------------------------------------------
__device__ __forceinline__ uint32_t smem_u32(const void* p) {
    uint32_t a;
    asm("{ .reg .u64 t; cvta.to.shared.u64 t, %1; cvt.u32.u64 %0, t; }" : "=r"(a) : "l"(p));
    return a;
}
__device__ __forceinline__ void cp_async16(uint32_t dst, const void* src) {
    asm volatile("cp.async.cg.shared.global [%0], [%1], 16;" :: "r"(dst), "l"(src));
}
__device__ __forceinline__ void cp_commit() { asm volatile("cp.async.commit_group;"); }
__device__ __forceinline__ void cp_wait0() { asm volatile("cp.async.wait_group 0;"); }
__device__ __forceinline__ void cp_wait1() { asm volatile("cp.async.wait_group 1;"); }

__device__ __forceinline__ void ldsm_x4(uint32_t& r0, uint32_t& r1, uint32_t& r2, uint32_t& r3,
                                        uint32_t addr) {
    asm volatile("ldmatrix.sync.aligned.m8n8.x4.shared.b16 {%0,%1,%2,%3}, [%4];"
                 : "=r"(r0), "=r"(r1), "=r"(r2), "=r"(r3) : "r"(addr));
}
__device__ __forceinline__ void mma16816(float& c0, float& c1, float& c2, float& c3,
                                         uint32_t a0, uint32_t a1, uint32_t a2, uint32_t a3,
                                         uint32_t b0, uint32_t b1) {
    asm volatile("mma.sync.aligned.m16n8k16.row.col.f32.f16.f16.f32 "
                 "{%0,%1,%2,%3}, {%4,%5,%6,%7}, {%8,%9}, {%0,%1,%2,%3};"
                 : "+f"(c0), "+f"(c1), "+f"(c2), "+f"(c3)
                 : "r"(a0), "r"(a1), "r"(a2), "r"(a3), "r"(b0), "r"(b1));
}

// swizzled byte offset within a tile of 64-half (128B) K-rows
__device__ __forceinline__ uint32_t sw_off(int row, int seg8) {
    return (uint32_t)row * 128u + (uint32_t)((seg8 ^ (row & 7)) * 16);
}

// ---------------------------------------------------------------------------
// Kernel A: adaptive avg pool to 4x4
// ---------------------------------------------------------------------------
__global__ void pool_kernel(const float* __restrict__ x) {
    __shared__ float seg[256];
    int bc = blockIdx.x, t = threadIdx.x;
    int row = t >> 2, q = t & 3;
    const float4* b4 = reinterpret_cast<const float4*>(x + ((size_t)bc * H + row) * W + q * 16);
    float s = 0.f;
#pragma unroll
    for (int i = 0; i < 4; i++) { float4 v = b4[i]; s += v.x + v.y + v.z + v.w; }
    seg[t] = s;
    __syncthreads();
    if (t < 16) {
        int pr = t >> 2, pc = t & 3;
        float acc = 0.f;
#pragma unroll
        for (int r = 0; r < 16; r++) acc += seg[(pr * 16 + r) * 4 + pc];
        g_pooled[bc * 16 + t] = acc * (1.0f / 256.0f);
    }
}

// ---------------------------------------------------------------------------
// Kernel B: routing MLP
// ---------------------------------------------------------------------------
__global__ void route_kernel(const float* __restrict__ rconv_w,
                             const float* __restrict__ rconv_b,
                             const float* __restrict__ fc_w,
                             const float* __restrict__ fc_b) {
    __shared__ float sp[CIN * 16];
    __shared__ float sy1[RC * 16];
    int b = blockIdx.x, t = threadIdx.x;
#pragma unroll
    for (int i = 0; i < 16; i++)
        sp[t + i * 256] = g_pooled[b * CIN * 16 + t + i * 256];
    __syncthreads();
    {
        int r = t >> 4, p = t & 15;
        float s = rconv_b[r];
        const float* wrow = rconv_w + r * CIN;
#pragma unroll 8
        for (int c = 0; c < CIN; c++) s = fmaf(sp[c * 16 + p], wrow[c], s);
        sy1[r * 16 + p] = fmaxf(s, 0.f);
    }
    __syncthreads();
#pragma unroll
    for (int kk = 0; kk < NE; kk++) {
        int e = kk * 256 + t;
        float s = fc_b[e];
        const float* wrow = fc_w + (size_t)e * 256;
#pragma unroll 8
        for (int m = 0; m < 256; m++) s = fmaf(sy1[m], wrow[m], s);
        s = fmaxf(s, 0.f);
        g_route[b * (NE * CIN) + e] = 1.0f / (1.0f + expf(-s));
    }
}

// ---------------------------------------------------------------------------
// Kernel C: combine expert weights -> fp16 in A layout
// ---------------------------------------------------------------------------
__global__ void wsplit_kernel(const float* __restrict__ ew) {
    int idx = blockIdx.x * blockDim.x + threadIdx.x;   // 0..65535
    int o = idx >> 8, c = idx & 255;
    float w0[3][9];
#pragma unroll
    for (int k = 0; k < 3; k++)
#pragma unroll
        for (int t = 0; t < 9; t++)
            w0[k][t] = ew[(((size_t)k * COUT + o) * CIN + c) * 9 + t];
    int half = o >> 7, m = o & 127, q = c >> 6, cc = c & 63;
    for (int b = 0; b < B; b++) {
        float r0 = g_route[b * 768 + 0 * 256 + c];
        float r1 = g_route[b * 768 + 1 * 256 + c];
        float r2 = g_route[b * 768 + 2 * 256 + c];
#pragma unroll
        for (int t = 0; t < 9; t++) {
            float w = fmaf(r2, w0[2][t], fmaf(r1, w0[1][t], r0 * w0[0][t]));
            size_t off = ((((size_t)(b * 2 + half) * 9 + t) * 4 + q) * 128 + m) * 64 + cc;
            g_wh[off] = __float2half(w);
        }
    }
}

// ---------------------------------------------------------------------------
// Kernel Z: zero only the padded borders of g_xt_h
// ---------------------------------------------------------------------------
__global__ void zero_border() {
    int i = blockIdx.x * 256 + threadIdx.x;
    int total = 16 * 4 * 66 * 32;
    if (i >= total) return;
    int seg = i & 31;
    int idx = (i >> 5) % 66;
    int side = (i >> 5) / 66 % 4;
    int b = i / (4 * 66 * 32);
    int yy, xx;
    if (side == 0)      { yy = 0;   xx = idx; }
    else if (side == 1) { yy = 65;  xx = idx; }
    else if (side == 2) { yy = idx; xx = 0;  }
    else                { yy = idx; xx = 65; }
    size_t off = (((size_t)b * 66 + yy) * 66 + xx) * 256 + seg * 8;
    reinterpret_cast<uint4*>(&g_xt_h[off])[0] = make_uint4(0, 0, 0, 0);
}

// ---------------------------------------------------------------------------
// Kernel X: transpose + pad + fp16 convert of x  ->  [b][yy][xx][c]
// ---------------------------------------------------------------------------
__global__ void xprep_kernel(const float* __restrict__ x) {
    __shared__ float ti[32][65];
    int c0 = blockIdx.x * 32, y = blockIdx.y, b = blockIdx.z;
    int t = threadIdx.x;
    {
        int cc = t >> 3, xg = t & 7;
        const float4* src = reinterpret_cast<const float4*>(
            x + (((size_t)b * CIN + c0 + cc) * H + y) * W + xg * 8);
        float4 v0 = src[0], v1 = src[1];
        ti[cc][xg * 8 + 0] = v0.x; ti[cc][xg * 8 + 1] = v0.y;
        ti[cc][xg * 8 + 2] = v0.z; ti[cc][xg * 8 + 3] = v0.w;
        ti[cc][xg * 8 + 4] = v1.x; ti[cc][xg * 8 + 5] = v1.y;
        ti[cc][xg * 8 + 6] = v1.z; ti[cc][xg * 8 + 7] = v1.w;
    }
    __syncthreads();
    int xx = t >> 2, cg = t & 3;
    __half h8[8];
#pragma unroll
    for (int j = 0; j < 8; j++)
        h8[j] = __float2half(ti[cg * 8 + j][xx]);
    size_t off = (((size_t)b * 66 + (y + 1)) * 66 + (xx + 1)) * 256 + c0 + cg * 8;
    *reinterpret_cast<uint4*>(&g_xt_h[off]) = *reinterpret_cast<const uint4*>(h8);
}

// ---------------------------------------------------------------------------
// Main conv kernel: warp-MMA fp16 shift-GEMM, XOR-swizzled smem, 2 CTAs/SM.
// CTA: M=128 couts x N=128 px (2 output rows). 8 warps (2x4), warp 64x32.
// ---------------------------------------------------------------------------
#define SB_BYTES  (4 * 66 * 64 * 2)        // 33792
#define SA_BYTES  (128 * 64 * 2)           // 16384
#define SMEM_TOTAL (2 * SB_BYTES + 2 * SA_BYTES)   // 100352

__global__ void __launch_bounds__(256, 2)
conv_mma_kernel(float* __restrict__ out) {
    extern __shared__ __align__(128) char smem[];
    uint32_t sB = smem_u32(smem);            // two buffers of SB_BYTES
    uint32_t sA = sB + 2 * SB_BYTES;         // two buffers of SA_BYTES

    int tid = threadIdx.x;
    int wid = tid >> 5, l = tid & 31;
    int warp_m = wid >> 2;                   // 0..1
    int warp_n = wid & 3;                    // 0..3

    int ntile = blockIdx.x;                  // 0..31
    int half  = blockIdx.y;                  // 0..1
    int b     = blockIdx.z;                  // 0..15
    int y0    = ntile * 2;

    // A lane geometry (xor key invariant across mf: 16 ≡ 0 mod 8)
    int aRow    = warp_m * 64 + ((l >> 3) & 1) * 8 + (l & 7);   // 0..127
    uint32_t aRowByte = (uint32_t)aRow * 128u;
    int aKey    = aRow & 7;
    int kbitA   = (l >> 4) & 1;

    // B lane geometry
    int bTileRow[2];
    int kbitB = (l >> 3) & 1;
#pragma unroll
    for (int g = 0; g < 2; g++) {
        int pix = warp_n * 32 + g * 16 + ((l >> 4) & 1) * 8 + (l & 7);
        int rb = pix >> 6, cb = pix & 63;
        bTileRow[g] = rb * 66 + cb;
    }

    float acc[4][4][4];
#pragma unroll
    for (int i = 0; i < 4; i++)
#pragma unroll
        for (int j = 0; j < 4; j++)
#pragma unroll
            for (int k = 0; k < 4; k++) acc[i][j][k] = 0.f;

    const __half* wbase = g_wh + (size_t)(b * 2 + half) * 9 * 4 * 128 * 64;

    auto loadB = [&](int cc, int buf) {
        uint32_t dst = sB + buf * SB_BYTES;
        int c0 = cc * 64;
        for (int i = tid; i < 264 * 8; i += 256) {
            int row = i >> 3, seg = i & 7;
            int gy = y0 + (row / 66), gx = row % 66;
            size_t goff = (((size_t)b * 66 + gy) * 66 + gx) * 256 + c0 + seg * 8;
            cp_async16(dst + sw_off(row, seg), g_xt_h + goff);
        }
    };
    auto loadA = [&](int pos, int cc, int buf) {
        uint32_t dst = sA + buf * SA_BYTES;
        for (int i = tid; i < 1024; i += 256) {
            int row = i >> 3, seg = i & 7;
            const __half* src = wbase + (((size_t)(pos * 4 + cc)) * 128 + row) * 64 + seg * 8;
            cp_async16(dst + sw_off(row, seg), src);
        }
    };

    loadB(0, 0);
    loadA(0, 0, 0);
    cp_commit();
    cp_wait0();
    __syncthreads();

    for (int cc = 0; cc < 4; cc++) {
        for (int pos = 0; pos < 9; pos++) {
            int step = cc * 9 + pos;
            uint32_t aBase = sA + (step & 1) * SA_BYTES;
            uint32_t bBase = sB + (cc & 1) * SB_BYTES;
            bool bpend = false;

            if (pos < 8) {
                loadA(pos + 1, cc, (step + 1) & 1);
                cp_commit();
                if (pos == 7 && cc < 3) {
                    loadB(cc + 1, (cc + 1) & 1);
                    cp_commit();
                    bpend = true;
                }
            } else if (cc < 3) {
                loadA(0, cc + 1, (step + 1) & 1);
                cp_commit();
            }

            int ky = pos / 3, kx = pos % 3;
            int posRow = ky * 66 + kx;

            // per-pos B row addressing (xor key varies with pos)
            uint32_t bRowByte[2];
            int bKey[2];
#pragma unroll
            for (int g = 0; g < 2; g++) {
                int tr = bTileRow[g] + posRow;
                bRowByte[g] = (uint32_t)tr * 128u;
                bKey[g] = tr & 7;
            }

#pragma unroll
            for (int ks = 0; ks < 4; ks++) {
                uint32_t a0[4], a1[4], a2[4], a3[4];
                uint32_t aseg = (uint32_t)(((ks * 2 + kbitA) ^ aKey) * 16);
#pragma unroll
                for (int mf = 0; mf < 4; mf++) {
                    uint32_t addr = aBase + aRowByte + (uint32_t)(mf * 16 * 128) + aseg;
                    ldsm_x4(a0[mf], a1[mf], a2[mf], a3[mf], addr);
                }
                uint32_t bh[8];
#pragma unroll
                for (int g = 0; g < 2; g++) {
                    uint32_t addr = bBase + bRowByte[g] +
                                    (uint32_t)(((ks * 2 + kbitB) ^ bKey[g]) * 16);
                    ldsm_x4(bh[g * 4 + 0], bh[g * 4 + 1], bh[g * 4 + 2], bh[g * 4 + 3], addr);
                }
#pragma unroll
                for (int mf = 0; mf < 4; mf++) {
#pragma unroll
                    for (int nf = 0; nf < 4; nf++) {
                        int g = nf >> 1, pr = (nf & 1) * 2;
                        mma16816(acc[mf][nf][0], acc[mf][nf][1], acc[mf][nf][2], acc[mf][nf][3],
                                 a0[mf], a1[mf], a2[mf], a3[mf],
                                 bh[g * 4 + pr], bh[g * 4 + pr + 1]);
                    }
                }
            }

            if (bpend) cp_wait1();
            else       cp_wait0();
            __syncthreads();
        }
    }

    // ---- epilogue ----
#pragma unroll
    for (int mf = 0; mf < 4; mf++) {
        int o = half * 128 + warp_m * 64 + mf * 16 + (l >> 2);
#pragma unroll
        for (int nf = 0; nf < 4; nf++) {
            int p = warp_n * 32 + nf * 8 + (l & 3) * 2;
            int y = y0 + (p >> 6), xcol = p & 63;
            float* base0 = out + (((size_t)b * COUT + o) * H + y) * W + xcol;
            float* base1 = out + (((size_t)b * COUT + o + 8) * H + y) * W + xcol;
            reinterpret_cast<float2*>(base0)[0] = make_float2(acc[mf][nf][0], acc[mf][nf][1]);
            reinterpret_cast<float2*>(base1)[0] = make_float2(acc[mf][nf][2], acc[mf][nf][3]);
        }
    }
}

// ---------------------------------------------------------------------------
extern "C" void kernel_launch(void* const* d_in, const int* in_sizes, int n_in,
                              void* d_out, int out_size) {
    const float* x   = (const float*)d_in[0];
    const float* ew  = (const float*)d_in[1];
    const float* rcw = (const float*)d_in[2];
    const float* rcb = (const float*)d_in[3];
    const float* fcw = (const float*)d_in[4];
    const float* fcb = (const float*)d_in[5];
    float* out = (float*)d_out;

    static bool attr_set = false;
    if (!attr_set) {
        cudaFuncSetAttribute(conv_mma_kernel, cudaFuncAttributeMaxDynamicSharedMemorySize,
                             SMEM_TOTAL);
        attr_set = true;
    }

    {
        int total = 16 * 4 * 66 * 32;
        zero_border<<<(total + 255) / 256, 256>>>();
    }
    pool_kernel<<<B * CIN, 256>>>(x);
    route_kernel<<<B, 256>>>(rcw, rcb, fcw, fcb);
    wsplit_kernel<<<256, 256>>>(ew);
    {
        dim3 g(8, 64, 16);
        xprep_kernel<<<g, 256>>>(x);
    }
    {
        dim3 g(32, 2, 16);
        conv_mma_kernel<<<g, 256, SMEM_TOTAL>>>(out);
    }
}